// round 15
// baseline (speedup 1.0000x reference)
#include <cuda_runtime.h>
#include <cuda_fp16.h>
#include <cstdint>
#include <cstddef>

// Problem constants
#define S_LEN   2048
#define HDIM    2048
#define NHEADS  16
#define HD      128
#define BATCH   2
#define QKV_N   6144
#define SCALE   0.08838834764831845f

// GEMM smem: 4 stages x (A 128x40h + B 128x40h)
#define GSTR_H      40
#define GSTAGE_H    (2 * 128 * GSTR_H)      // 10240 halves
#define GEMM_SMEM   (4 * GSTAGE_H * 2)      // 81920 B

// Attention smem: Q[128x136h] | stage{K[64x136h], Vt[128x72h]} x2
#define AT_STR_H    136
#define VT_STR_H    72
#define ATT_Q_H     (128 * AT_STR_H)
#define ATT_K_H     (64 * AT_STR_H)
#define ATT_VT_H    (128 * VT_STR_H)
#define ATT_STAGE_H (ATT_K_H + ATT_VT_H)
#define ATT_SMEM_B  ((ATT_Q_H + 2 * ATT_STAGE_H) * 2)  // 106496 B

// Scratch (device globals — allocation-free), all fp16
__device__ __half g_hid[(size_t)BATCH * S_LEN * HDIM];
__device__ __half g_qkv[(size_t)BATCH * S_LEN * QKV_N];
__device__ __half g_att[(size_t)BATCH * S_LEN * HDIM];
__device__ __half g_wta[(size_t)QKV_N * HDIM];
__device__ __half g_wtp[(size_t)HDIM * HDIM];
__device__ __half g_vt[(size_t)BATCH * NHEADS * HD * S_LEN];  // V^T per head [d][k]

__device__ __forceinline__ uint32_t smem_u32(const void* p) {
    uint32_t a;
    asm("{ .reg .u64 t; cvta.to.shared.u64 t, %1; cvt.u32.u64 %0, t; }" : "=r"(a) : "l"(p));
    return a;
}
__device__ __forceinline__ void cp16(uint32_t dst, const void* src) {
    asm volatile("cp.async.cg.shared.global [%0], [%1], 16;" :: "r"(dst), "l"(src));
}
#define CP_COMMIT() asm volatile("cp.async.commit_group;" ::: "memory")
#define CP_WAIT0()  asm volatile("cp.async.wait_group 0;" ::: "memory")

// m16n8k16 fp16 MMA, fp32 accumulate
__device__ __forceinline__ void mma_f16(float* c, const uint32_t* a, const uint32_t* b) {
    asm volatile(
        "mma.sync.aligned.m16n8k16.row.col.f32.f16.f16.f32 "
        "{%0,%1,%2,%3}, {%4,%5,%6,%7}, {%8,%9}, {%0,%1,%2,%3};"
        : "+f"(c[0]), "+f"(c[1]), "+f"(c[2]), "+f"(c[3])
        : "r"(a[0]), "r"(a[1]), "r"(a[2]), "r"(a[3]), "r"(b[0]), "r"(b[1]));
}
__device__ __forceinline__ void ldsm4(uint32_t* r, uint32_t addr) {
    asm volatile("ldmatrix.sync.aligned.m8n8.x4.shared.b16 {%0,%1,%2,%3}, [%4];"
                 : "=r"(r[0]), "=r"(r[1]), "=r"(r[2]), "=r"(r[3]) : "r"(addr));
}
__device__ __forceinline__ uint32_t pack_h2(float a, float b) {
    __half2 h = __floats2half2_rn(a, b);
    return *reinterpret_cast<uint32_t*>(&h);
}

// ---------------------------------------------------------------------------
// fp32 -> fp16 elementwise (8 per thread)
// ---------------------------------------------------------------------------
__global__ void f2h_kernel(const float* __restrict__ in, __half* __restrict__ out)
{
    const size_t i = ((size_t)blockIdx.x * blockDim.x + threadIdx.x) * 8;
    float4 v0 = *(const float4*)(in + i);
    float4 v1 = *(const float4*)(in + i + 4);
    __half2 h[4];
    h[0] = __floats2half2_rn(v0.x, v0.y);
    h[1] = __floats2half2_rn(v0.z, v0.w);
    h[2] = __floats2half2_rn(v1.x, v1.y);
    h[3] = __floats2half2_rn(v1.z, v1.w);
    *(uint4*)(out + i) = *(uint4*)h;
}

// ---------------------------------------------------------------------------
// Transpose fp32 -> fp16: out[C][R] = h(in[R][C])
// ---------------------------------------------------------------------------
__global__ void transpose_h_kernel(const float* __restrict__ in, __half* __restrict__ out,
                                   int R, int C)
{
    __shared__ float t[32][33];
    const int bx = blockIdx.x * 32;
    const int by = blockIdx.y * 32;
#pragma unroll
    for (int i = 0; i < 32; i += 8)
        t[threadIdx.y + i][threadIdx.x] =
            in[(size_t)(by + threadIdx.y + i) * C + bx + threadIdx.x];
    __syncthreads();
#pragma unroll
    for (int i = 0; i < 32; i += 8)
        out[(size_t)(bx + threadIdx.y + i) * R + by + threadIdx.x] =
            __float2half_rn(t[threadIdx.x][threadIdx.y + i]);
}

// ---------------------------------------------------------------------------
// V transpose (fp16): g_vt[(b*16+nh)*128 + d][k] = Vh[k][d]
// ---------------------------------------------------------------------------
__global__ void vtranspose_kernel(void)
{
    __shared__ __half t[32][34];
    const int tk = blockIdx.x * 32;
    const int td = blockIdx.y * 32;
    const int h  = blockIdx.z;
    const int b  = h >> 4;
    const int nh = h & 15;

    const size_t base_bh = ((size_t)b * S_LEN + (size_t)nh * HD) * QKV_N + 2 * HDIM;
#pragma unroll
    for (int i = 0; i < 32; i += 8) {
        const int k = tk + threadIdx.y + i;
        t[threadIdx.y + i][threadIdx.x] =
            g_qkv[base_bh + (size_t)(k >> 4) * QKV_N + ((k & 15) << 7) + td + threadIdx.x];
    }
    __syncthreads();
#pragma unroll
    for (int i = 0; i < 32; i += 8)
        g_vt[((size_t)h * HD + td + threadIdx.y + i) * S_LEN + tk + threadIdx.x] =
            t[threadIdx.x][threadIdx.y + i];
}

// ---------------------------------------------------------------------------
// fp16 mma.sync GEMM (R13 best config): 256 threads, warp 64x32, cp.async
// 4-stage, pair-chunk barriers, LDSM fragments. C = A @ Bt^T + bias.
// ---------------------------------------------------------------------------
__global__ __launch_bounds__(256, 2)
void gemm_f16_kernel(const __half* __restrict__ A, const __half* __restrict__ Bt,
                     const float* __restrict__ bias, void* Cv,
                     int M, int N, int K, int out_half)
{
    extern __shared__ __half smh[];
    const uint32_t smb = smem_u32(smh);
    const int tid    = threadIdx.x;
    const int lane   = tid & 31;
    const int wid    = tid >> 5;
    const int g      = lane >> 2;
    const int t      = lane & 3;
    const int warp_m = wid & 1;
    const int warp_n = wid >> 1;
    const int m0     = blockIdx.y << 7;
    const int n0     = blockIdx.x << 7;

    const __half* Ap = A  + (size_t)m0 * K;
    const __half* Bp = Bt + (size_t)n0 * K;

    const int nchunks = K >> 5;       // 32 halves per chunk
    const int npairs  = nchunks >> 1;
    const int fr  = tid >> 2;         // fill row 0..63 (x2)
    const int fc  = tid & 3;          // 16B chunk within 64B row

    const int rowin = lane & 7;
    const int rsel  = (lane >> 3) & 1;
    const int csel  = (lane >> 4) & 1;

    const uint32_t a_lane_off =
        (uint32_t)(((warp_m * 64) + rsel * 8 + rowin) * GSTR_H + csel * 8) * 2;
    const uint32_t b_lane_off =
        (uint32_t)(((warp_n * 32) + csel * 8 + rowin) * GSTR_H + rsel * 8) * 2;

    auto fill = [&](int c, int s) {
        if (c < nchunks) {
            const int kc = c << 5;
            const uint32_t sa = smb + (uint32_t)s * GSTAGE_H * 2;
#pragma unroll
            for (int i = 0; i < 2; i++) {
                const int r = fr + (i << 6);
                cp16(sa + (uint32_t)(r * GSTR_H + fc * 8) * 2,
                     Ap + (size_t)r * K + kc + fc * 8);
                cp16(sa + (uint32_t)(128 * GSTR_H + r * GSTR_H + fc * 8) * 2,
                     Bp + (size_t)r * K + kc + fc * 8);
            }
        }
        CP_COMMIT();
    };

    float acc[4][4][4];
#pragma unroll
    for (int mt = 0; mt < 4; mt++)
#pragma unroll
        for (int nt = 0; nt < 4; nt++)
#pragma unroll
            for (int k = 0; k < 4; k++) acc[mt][nt][k] = 0.0f;

    float2 bv[4];
#pragma unroll
    for (int nt = 0; nt < 4; nt++)
        bv[nt] = *(const float2*)(bias + n0 + warp_n * 32 + nt * 8 + 2 * t);

    fill(0, 0); fill(1, 1);

    for (int p = 0; p < npairs; ++p) {
        const int c0 = p << 1;
        CP_WAIT0();
        __syncthreads();
        fill(c0 + 2, (c0 + 2) & 3);
        fill(c0 + 3, (c0 + 3) & 3);

#pragma unroll
        for (int half = 0; half < 2; ++half) {
            const int s = (c0 + half) & 3;
            const uint32_t sAb = smb + (uint32_t)s * GSTAGE_H * 2;
            const uint32_t sBb = sAb + 128 * GSTR_H * 2;
#pragma unroll
            for (int ks = 0; ks < 2; ks++) {          // k16 steps
                const uint32_t kb = (uint32_t)ks * 32;  // 16 halves
                uint32_t afr[4][4], bfr[4][2];
#pragma unroll
                for (int mt = 0; mt < 4; mt++)
                    ldsm4(afr[mt], sAb + a_lane_off + kb +
                                   (uint32_t)(mt * 16 * GSTR_H) * 2);
#pragma unroll
                for (int nt2 = 0; nt2 < 2; nt2++) {
                    uint32_t rr[4];
                    ldsm4(rr, sBb + b_lane_off + kb +
                              (uint32_t)(nt2 * 16 * GSTR_H) * 2);
                    bfr[2 * nt2][0]     = rr[0];
                    bfr[2 * nt2][1]     = rr[1];
                    bfr[2 * nt2 + 1][0] = rr[2];
                    bfr[2 * nt2 + 1][1] = rr[3];
                }
#pragma unroll
                for (int mt = 0; mt < 4; mt++)
#pragma unroll
                    for (int nt = 0; nt < 4; nt++)
                        mma_f16(acc[mt][nt], afr[mt], bfr[nt]);
            }
        }
    }

#pragma unroll
    for (int mt = 0; mt < 4; mt++) {
        const int row0 = m0 + warp_m * 64 + mt * 16 + g;
#pragma unroll
        for (int nt = 0; nt < 4; nt++) {
            const int col = n0 + warp_n * 32 + nt * 8 + 2 * t;
            const float x0 = acc[mt][nt][0] + bv[nt].x;
            const float y0 = acc[mt][nt][1] + bv[nt].y;
            const float x1 = acc[mt][nt][2] + bv[nt].x;
            const float y1 = acc[mt][nt][3] + bv[nt].y;
            if (out_half) {
                __half* C = (__half*)Cv;
                *(__half2*)(C + (size_t)row0 * N + col)       = __floats2half2_rn(x0, y0);
                *(__half2*)(C + (size_t)(row0 + 8) * N + col) = __floats2half2_rn(x1, y1);
            } else {
                float* C = (float*)Cv;
                *(float2*)(C + (size_t)row0 * N + col)       = make_float2(x0, y0);
                *(float2*)(C + (size_t)(row0 + 8) * N + col) = make_float2(x1, y1);
            }
        }
    }
}

// ---------------------------------------------------------------------------
// Flash attention, fp16 mma.sync m16n8k16 — register-dieted for 2 CTAs/SM:
// pexp folded into sacc (in-place exponentials), __launch_bounds__(256, 2).
// ---------------------------------------------------------------------------
__global__ __launch_bounds__(256, 2)
void attn_mma_kernel(__half* __restrict__ att_out)
{
    extern __shared__ __half smh[];
    const uint32_t smb = smem_u32(smh);

    const int qt  = 15 - blockIdx.x;     // heavy tiles first
    const int nh  = blockIdx.y;
    const int b   = blockIdx.z;
    const int q0  = qt << 7;
    const int tid = threadIdx.x;
    const int lane = tid & 31;
    const int wid  = tid >> 5;
    const int g    = lane >> 2;
    const int t    = lane & 3;

    const size_t base_bh = ((size_t)b * S_LEN + (size_t)nh * HD) * QKV_N;
    const __half* vt_base = g_vt + (size_t)(b * NHEADS + nh) * HD * S_LEN;

    const int rowin = lane & 7;
    const int rsel  = (lane >> 3) & 1;
    const int csel  = (lane >> 4) & 1;
    const uint32_t q_lane_off =
        (uint32_t)(((wid * 16) + rsel * 8 + rowin) * AT_STR_H + csel * 8) * 2;
    const uint32_t k_lane_off =
        (uint32_t)((csel * 8 + rowin) * AT_STR_H + rsel * 8) * 2;
    const uint32_t v_lane_off =
        (uint32_t)((csel * 8 + rowin) * VT_STR_H + rsel * 8) * 2;

    auto fill_stage = [&](int kt, int s) {
        const int k0 = kt << 6;
        const uint32_t kb = smb + (uint32_t)(ATT_Q_H + s * ATT_STAGE_H) * 2;
        const uint32_t vb = kb + (uint32_t)ATT_K_H * 2;
#pragma unroll
        for (int i = 0; i < 4; i++) {
            const int slot = tid + (i << 8);
            const int r  = slot >> 4;
            const int ch = slot & 15;
            const int kg = k0 + r;
            cp16(kb + (uint32_t)(r * AT_STR_H + ch * 8) * 2,
                 g_qkv + base_bh + (size_t)(kg >> 4) * QKV_N + ((kg & 15) << 7) +
                 HDIM + ch * 8);
        }
#pragma unroll
        for (int i = 0; i < 4; i++) {
            const int slot = tid + (i << 8);
            const int d  = slot >> 3;
            const int ch = slot & 7;
            cp16(vb + (uint32_t)(d * VT_STR_H + ch * 8) * 2,
                 vt_base + (size_t)d * S_LEN + k0 + ch * 8);
        }
        CP_COMMIT();
    };

#pragma unroll
    for (int i = 0; i < 8; i++) {
        const int slot = tid + (i << 8);
        const int r  = slot >> 4;
        const int ch = slot & 15;
        const int qg = q0 + r;
        cp16(smb + (uint32_t)(r * AT_STR_H + ch * 8) * 2,
             g_qkv + base_bh + (size_t)(qg >> 4) * QKV_N + ((qg & 15) << 7) + ch * 8);
    }
    fill_stage(0, 0);
    CP_WAIT0();
    __syncthreads();

    float O[16][4];
#pragma unroll
    for (int nt = 0; nt < 16; nt++)
#pragma unroll
        for (int k = 0; k < 4; k++) O[nt][k] = 0.0f;

    float m_run[2] = {-1e30f, -1e30f};
    float l_run[2] = {0.0f, 0.0f};

    const int nkt = (q0 + 128) >> 6;

    for (int kt = 0; kt < nkt; kt++) {
        const int s  = kt & 1;
        const int k0 = kt << 6;
        const uint32_t Kcb = smb + (uint32_t)(ATT_Q_H + s * ATT_STAGE_H) * 2;
        const uint32_t Vcb = Kcb + (uint32_t)ATT_K_H * 2;
        const bool pre = (kt + 1) < nkt;

        if (pre) fill_stage(kt + 1, s ^ 1);

        // ---- S = Q K^T (16x64 per warp), 8 k16-steps ----
        float sacc[8][4];
#pragma unroll
        for (int nt = 0; nt < 8; nt++)
#pragma unroll
            for (int k = 0; k < 4; k++) sacc[nt][k] = 0.0f;

#pragma unroll
        for (int ks = 0; ks < 8; ks++) {
            const uint32_t kb = (uint32_t)ks * 32;
            uint32_t a[4];
            ldsm4(a, smb + q_lane_off + kb);
#pragma unroll
            for (int nt2 = 0; nt2 < 4; nt2++) {
                uint32_t rr[4];
                ldsm4(rr, Kcb + k_lane_off + kb + (uint32_t)(nt2 * 16 * AT_STR_H) * 2);
                uint32_t b0[2] = {rr[0], rr[1]};
                uint32_t b1[2] = {rr[2], rr[3]};
                mma_f16(sacc[2 * nt2],     a, b0);
                mma_f16(sacc[2 * nt2 + 1], a, b1);
            }
        }

        // ---- online softmax; exponentials written back into sacc ----
        const bool crossing = (k0 + 63) > (q0 + (wid << 4));
        float corr[2];
#pragma unroll
        for (int r = 0; r < 2; r++) {
            const int qg = q0 + (wid << 4) + g + 8 * r;
            float rm = -1e30f;
#pragma unroll
            for (int nt = 0; nt < 8; nt++) {
#pragma unroll
                for (int j = 0; j < 2; j++) {
                    float v = sacc[nt][2 * r + j] * SCALE;
                    if (crossing && (k0 + nt * 8 + 2 * t + j) > qg) v = -1e9f;
                    sacc[nt][2 * r + j] = v;
                    rm = fmaxf(rm, v);
                }
            }
            rm = fmaxf(rm, __shfl_xor_sync(0xffffffffu, rm, 1));
            rm = fmaxf(rm, __shfl_xor_sync(0xffffffffu, rm, 2));

            const float mn = fmaxf(m_run[r], rm);
            corr[r] = __expf(m_run[r] - mn);
            m_run[r] = mn;

            float rs = 0.0f;
#pragma unroll
            for (int nt = 0; nt < 8; nt++) {
#pragma unroll
                for (int j = 0; j < 2; j++) {
                    const float p = __expf(sacc[nt][2 * r + j] - mn);
                    sacc[nt][2 * r + j] = p;   // in-place: P replaces scores
                    rs += p;
                }
            }
            rs += __shfl_xor_sync(0xffffffffu, rs, 1);
            rs += __shfl_xor_sync(0xffffffffu, rs, 2);
            l_run[r] = l_run[r] * corr[r] + rs;
        }
#pragma unroll
        for (int nt = 0; nt < 16; nt++) {
            O[nt][0] *= corr[0]; O[nt][1] *= corr[0];
            O[nt][2] *= corr[1]; O[nt][3] *= corr[1];
        }

        // ---- O += P V : P c-layout == fp16 A-layout (no shuffles) ----
#pragma unroll
        for (int ks = 0; ks < 4; ks++) {
            uint32_t a[4];
            a[0] = pack_h2(sacc[2 * ks][0],     sacc[2 * ks][1]);
            a[1] = pack_h2(sacc[2 * ks][2],     sacc[2 * ks][3]);
            a[2] = pack_h2(sacc[2 * ks + 1][0], sacc[2 * ks + 1][1]);
            a[3] = pack_h2(sacc[2 * ks + 1][2], sacc[2 * ks + 1][3]);
            const uint32_t kscol = (uint32_t)ks * 32;
#pragma unroll
            for (int nt2 = 0; nt2 < 8; nt2++) {
                uint32_t rr[4];
                ldsm4(rr, Vcb + v_lane_off + kscol +
                          (uint32_t)(nt2 * 16 * VT_STR_H) * 2);
                uint32_t b0[2] = {rr[0], rr[1]};
                uint32_t b1[2] = {rr[2], rr[3]};
                mma_f16(O[2 * nt2],     a, b0);
                mma_f16(O[2 * nt2 + 1], a, b1);
            }
        }

        CP_WAIT0();
        __syncthreads();
    }

#pragma unroll
    for (int r = 0; r < 2; r++) {
        const float inv = 1.0f / l_run[r];
        const int qg = q0 + (wid << 4) + g + 8 * r;
        __half* op = att_out + ((size_t)b * S_LEN + qg) * HDIM + nh * HD;
#pragma unroll
        for (int nt = 0; nt < 16; nt++) {
            __half2 h = __floats2half2_rn(O[nt][2 * r] * inv, O[nt][2 * r + 1] * inv);
            *(__half2*)(op + nt * 8 + 2 * t) = h;
        }
    }
}

// ---------------------------------------------------------------------------
// Launch
// ---------------------------------------------------------------------------
extern "C" void kernel_launch(void* const* d_in, const int* in_sizes, int n_in,
                              void* d_out, int out_size)
{
    const float* hidden = (const float*)d_in[0];
    const float* W_attn = (const float*)d_in[2];
    const float* b_attn = (const float*)d_in[3];
    const float* W_proj = (const float*)d_in[4];
    const float* b_proj = (const float*)d_in[5];
    float* out = (float*)d_out;

    __half *hid, *qkv, *att, *wta, *wtp;
    cudaGetSymbolAddress((void**)&hid, g_hid);
    cudaGetSymbolAddress((void**)&qkv, g_qkv);
    cudaGetSymbolAddress((void**)&att, g_att);
    cudaGetSymbolAddress((void**)&wta, g_wta);
    cudaGetSymbolAddress((void**)&wtp, g_wtp);

    const int M = BATCH * S_LEN;   // 4096

    // 0) Convert hidden to fp16; transpose+convert weights
    {
        const size_t n = (size_t)BATCH * S_LEN * HDIM;
        f2h_kernel<<<(int)(n / 8 / 256), 256>>>(hidden, hid);
        dim3 blk(32, 8);
        transpose_h_kernel<<<dim3(QKV_N / 32, HDIM / 32), blk>>>(W_attn, wta, HDIM, QKV_N);
        transpose_h_kernel<<<dim3(HDIM / 32, HDIM / 32), blk>>>(W_proj, wtp, HDIM, HDIM);
    }

    cudaFuncSetAttribute(gemm_f16_kernel,
                         cudaFuncAttributeMaxDynamicSharedMemorySize, GEMM_SMEM);

    // 1) QKV projection (fp16 out)
    gemm_f16_kernel<<<dim3(QKV_N / 128, M / 128), 256, GEMM_SMEM>>>(
        hid, wta, b_attn, qkv, M, QKV_N, HDIM, 1);

    // 1b) Per-head V transpose for PV ldmatrix path
    {
        dim3 blk(32, 8);
        vtranspose_kernel<<<dim3(S_LEN / 32, HD / 32, BATCH * NHEADS), blk>>>();
    }

    // 2) Attention (fp16 mma flash, 2 CTAs/SM)
    {
        cudaFuncSetAttribute(attn_mma_kernel,
                             cudaFuncAttributeMaxDynamicSharedMemorySize, ATT_SMEM_B);
        dim3 grid(S_LEN / 128, NHEADS, BATCH);
        attn_mma_kernel<<<grid, 256, ATT_SMEM_B>>>(att);
    }

    // 3) Output projection (fp32 out)
    gemm_f16_kernel<<<dim3(HDIM / 128, M / 128), 256, GEMM_SMEM>>>(
        att, wtp, b_proj, out, M, HDIM, HDIM, 0);
}

// round 16
// speedup vs baseline: 1.0540x; 1.0540x over previous
#include <cuda_runtime.h>
#include <cuda_fp16.h>
#include <cstdint>
#include <cstddef>

// Problem constants
#define S_LEN   2048
#define HDIM    2048
#define NHEADS  16
#define HD      128
#define BATCH   2
#define QKV_N   6144
// SCALE * log2(e): softmax runs in base-2 domain (exp2f), saving one FMA/exp.
#define SCALE2  0.12751649736230376f

// GEMM smem: 4 stages x (A 128x40h + B 128x40h)
#define GSTR_H      40
#define GSTAGE_H    (2 * 128 * GSTR_H)      // 10240 halves
#define GEMM_SMEM   (4 * GSTAGE_H * 2)      // 81920 B

// Attention smem: Q[128x136h] | stage{K[64x136h], Vt[128x72h]} x2
#define AT_STR_H    136
#define VT_STR_H    72
#define ATT_Q_H     (128 * AT_STR_H)
#define ATT_K_H     (64 * AT_STR_H)
#define ATT_VT_H    (128 * VT_STR_H)
#define ATT_STAGE_H (ATT_K_H + ATT_VT_H)
#define ATT_SMEM_B  ((ATT_Q_H + 2 * ATT_STAGE_H) * 2)  // 106496 B

// Scratch (device globals — allocation-free), all fp16
__device__ __half g_hid[(size_t)BATCH * S_LEN * HDIM];
__device__ __half g_qkv[(size_t)BATCH * S_LEN * QKV_N];
__device__ __half g_att[(size_t)BATCH * S_LEN * HDIM];
__device__ __half g_wta[(size_t)QKV_N * HDIM];
__device__ __half g_wtp[(size_t)HDIM * HDIM];
__device__ __half g_vt[(size_t)BATCH * NHEADS * HD * S_LEN];  // V^T per head [d][k]

__device__ __forceinline__ uint32_t smem_u32(const void* p) {
    uint32_t a;
    asm("{ .reg .u64 t; cvta.to.shared.u64 t, %1; cvt.u32.u64 %0, t; }" : "=r"(a) : "l"(p));
    return a;
}
__device__ __forceinline__ void cp16(uint32_t dst, const void* src) {
    asm volatile("cp.async.cg.shared.global [%0], [%1], 16;" :: "r"(dst), "l"(src));
}
#define CP_COMMIT() asm volatile("cp.async.commit_group;" ::: "memory")
#define CP_WAIT0()  asm volatile("cp.async.wait_group 0;" ::: "memory")

// m16n8k16 fp16 MMA, fp32 accumulate
__device__ __forceinline__ void mma_f16(float* c, const uint32_t* a, const uint32_t* b) {
    asm volatile(
        "mma.sync.aligned.m16n8k16.row.col.f32.f16.f16.f32 "
        "{%0,%1,%2,%3}, {%4,%5,%6,%7}, {%8,%9}, {%0,%1,%2,%3};"
        : "+f"(c[0]), "+f"(c[1]), "+f"(c[2]), "+f"(c[3])
        : "r"(a[0]), "r"(a[1]), "r"(a[2]), "r"(a[3]), "r"(b[0]), "r"(b[1]));
}
__device__ __forceinline__ void ldsm4(uint32_t* r, uint32_t addr) {
    asm volatile("ldmatrix.sync.aligned.m8n8.x4.shared.b16 {%0,%1,%2,%3}, [%4];"
                 : "=r"(r[0]), "=r"(r[1]), "=r"(r[2]), "=r"(r[3]) : "r"(addr));
}
__device__ __forceinline__ uint32_t pack_h2(float a, float b) {
    __half2 h = __floats2half2_rn(a, b);
    return *reinterpret_cast<uint32_t*>(&h);
}

// ---------------------------------------------------------------------------
// fp32 -> fp16 elementwise (8 per thread)
// ---------------------------------------------------------------------------
__global__ void f2h_kernel(const float* __restrict__ in, __half* __restrict__ out)
{
    const size_t i = ((size_t)blockIdx.x * blockDim.x + threadIdx.x) * 8;
    float4 v0 = *(const float4*)(in + i);
    float4 v1 = *(const float4*)(in + i + 4);
    __half2 h[4];
    h[0] = __floats2half2_rn(v0.x, v0.y);
    h[1] = __floats2half2_rn(v0.z, v0.w);
    h[2] = __floats2half2_rn(v1.x, v1.y);
    h[3] = __floats2half2_rn(v1.z, v1.w);
    *(uint4*)(out + i) = *(uint4*)h;
}

// ---------------------------------------------------------------------------
// Transpose fp32 -> fp16: out[C][R] = h(in[R][C])
// ---------------------------------------------------------------------------
__global__ void transpose_h_kernel(const float* __restrict__ in, __half* __restrict__ out,
                                   int R, int C)
{
    __shared__ float t[32][33];
    const int bx = blockIdx.x * 32;
    const int by = blockIdx.y * 32;
#pragma unroll
    for (int i = 0; i < 32; i += 8)
        t[threadIdx.y + i][threadIdx.x] =
            in[(size_t)(by + threadIdx.y + i) * C + bx + threadIdx.x];
    __syncthreads();
#pragma unroll
    for (int i = 0; i < 32; i += 8)
        out[(size_t)(bx + threadIdx.y + i) * R + by + threadIdx.x] =
            __float2half_rn(t[threadIdx.x][threadIdx.y + i]);
}

// ---------------------------------------------------------------------------
// V transpose (fp16): g_vt[(b*16+nh)*128 + d][k] = Vh[k][d]
// ---------------------------------------------------------------------------
__global__ void vtranspose_kernel(void)
{
    __shared__ __half t[32][34];
    const int tk = blockIdx.x * 32;
    const int td = blockIdx.y * 32;
    const int h  = blockIdx.z;
    const int b  = h >> 4;
    const int nh = h & 15;

    const size_t base_bh = ((size_t)b * S_LEN + (size_t)nh * HD) * QKV_N + 2 * HDIM;
#pragma unroll
    for (int i = 0; i < 32; i += 8) {
        const int k = tk + threadIdx.y + i;
        t[threadIdx.y + i][threadIdx.x] =
            g_qkv[base_bh + (size_t)(k >> 4) * QKV_N + ((k & 15) << 7) + td + threadIdx.x];
    }
    __syncthreads();
#pragma unroll
    for (int i = 0; i < 32; i += 8)
        g_vt[((size_t)h * HD + td + threadIdx.y + i) * S_LEN + tk + threadIdx.x] =
            t[threadIdx.x][threadIdx.y + i];
}

// ---------------------------------------------------------------------------
// fp16 mma.sync GEMM (R13 best config): 256 threads, warp 64x32, cp.async
// 4-stage, pair-chunk barriers, LDSM fragments. C = A @ Bt^T + bias.
// ---------------------------------------------------------------------------
__global__ __launch_bounds__(256, 2)
void gemm_f16_kernel(const __half* __restrict__ A, const __half* __restrict__ Bt,
                     const float* __restrict__ bias, void* Cv,
                     int M, int N, int K, int out_half)
{
    extern __shared__ __half smh[];
    const uint32_t smb = smem_u32(smh);
    const int tid    = threadIdx.x;
    const int lane   = tid & 31;
    const int wid    = tid >> 5;
    const int g      = lane >> 2;
    const int t      = lane & 3;
    const int warp_m = wid & 1;
    const int warp_n = wid >> 1;
    const int m0     = blockIdx.y << 7;
    const int n0     = blockIdx.x << 7;

    const __half* Ap = A  + (size_t)m0 * K;
    const __half* Bp = Bt + (size_t)n0 * K;

    const int nchunks = K >> 5;       // 32 halves per chunk
    const int npairs  = nchunks >> 1;
    const int fr  = tid >> 2;         // fill row 0..63 (x2)
    const int fc  = tid & 3;          // 16B chunk within 64B row

    const int rowin = lane & 7;
    const int rsel  = (lane >> 3) & 1;
    const int csel  = (lane >> 4) & 1;

    const uint32_t a_lane_off =
        (uint32_t)(((warp_m * 64) + rsel * 8 + rowin) * GSTR_H + csel * 8) * 2;
    const uint32_t b_lane_off =
        (uint32_t)(((warp_n * 32) + csel * 8 + rowin) * GSTR_H + rsel * 8) * 2;

    auto fill = [&](int c, int s) {
        if (c < nchunks) {
            const int kc = c << 5;
            const uint32_t sa = smb + (uint32_t)s * GSTAGE_H * 2;
#pragma unroll
            for (int i = 0; i < 2; i++) {
                const int r = fr + (i << 6);
                cp16(sa + (uint32_t)(r * GSTR_H + fc * 8) * 2,
                     Ap + (size_t)r * K + kc + fc * 8);
                cp16(sa + (uint32_t)(128 * GSTR_H + r * GSTR_H + fc * 8) * 2,
                     Bp + (size_t)r * K + kc + fc * 8);
            }
        }
        CP_COMMIT();
    };

    float acc[4][4][4];
#pragma unroll
    for (int mt = 0; mt < 4; mt++)
#pragma unroll
        for (int nt = 0; nt < 4; nt++)
#pragma unroll
            for (int k = 0; k < 4; k++) acc[mt][nt][k] = 0.0f;

    float2 bv[4];
#pragma unroll
    for (int nt = 0; nt < 4; nt++)
        bv[nt] = *(const float2*)(bias + n0 + warp_n * 32 + nt * 8 + 2 * t);

    fill(0, 0); fill(1, 1);

    for (int p = 0; p < npairs; ++p) {
        const int c0 = p << 1;
        CP_WAIT0();
        __syncthreads();
        fill(c0 + 2, (c0 + 2) & 3);
        fill(c0 + 3, (c0 + 3) & 3);

#pragma unroll
        for (int half = 0; half < 2; ++half) {
            const int s = (c0 + half) & 3;
            const uint32_t sAb = smb + (uint32_t)s * GSTAGE_H * 2;
            const uint32_t sBb = sAb + 128 * GSTR_H * 2;
#pragma unroll
            for (int ks = 0; ks < 2; ks++) {          // k16 steps
                const uint32_t kb = (uint32_t)ks * 32;  // 16 halves
                uint32_t afr[4][4], bfr[4][2];
#pragma unroll
                for (int mt = 0; mt < 4; mt++)
                    ldsm4(afr[mt], sAb + a_lane_off + kb +
                                   (uint32_t)(mt * 16 * GSTR_H) * 2);
#pragma unroll
                for (int nt2 = 0; nt2 < 2; nt2++) {
                    uint32_t rr[4];
                    ldsm4(rr, sBb + b_lane_off + kb +
                              (uint32_t)(nt2 * 16 * GSTR_H) * 2);
                    bfr[2 * nt2][0]     = rr[0];
                    bfr[2 * nt2][1]     = rr[1];
                    bfr[2 * nt2 + 1][0] = rr[2];
                    bfr[2 * nt2 + 1][1] = rr[3];
                }
#pragma unroll
                for (int mt = 0; mt < 4; mt++)
#pragma unroll
                    for (int nt = 0; nt < 4; nt++)
                        mma_f16(acc[mt][nt], afr[mt], bfr[nt]);
            }
        }
    }

#pragma unroll
    for (int mt = 0; mt < 4; mt++) {
        const int row0 = m0 + warp_m * 64 + mt * 16 + g;
#pragma unroll
        for (int nt = 0; nt < 4; nt++) {
            const int col = n0 + warp_n * 32 + nt * 8 + 2 * t;
            const float x0 = acc[mt][nt][0] + bv[nt].x;
            const float y0 = acc[mt][nt][1] + bv[nt].y;
            const float x1 = acc[mt][nt][2] + bv[nt].x;
            const float y1 = acc[mt][nt][3] + bv[nt].y;
            if (out_half) {
                __half* C = (__half*)Cv;
                *(__half2*)(C + (size_t)row0 * N + col)       = __floats2half2_rn(x0, y0);
                *(__half2*)(C + (size_t)(row0 + 8) * N + col) = __floats2half2_rn(x1, y1);
            } else {
                float* C = (float*)Cv;
                *(float2*)(C + (size_t)row0 * N + col)       = make_float2(x0, y0);
                *(float2*)(C + (size_t)(row0 + 8) * N + col) = make_float2(x1, y1);
            }
        }
    }
}

// ---------------------------------------------------------------------------
// Flash attention, fp16 mma.sync m16n8k16 (R13 structure: 1 CTA/SM, no reg
// cap). Exponentials in base-2 domain (exp2f) and written in place into sacc.
// ---------------------------------------------------------------------------
__global__ __launch_bounds__(256, 1)
void attn_mma_kernel(__half* __restrict__ att_out)
{
    extern __shared__ __half smh[];
    const uint32_t smb = smem_u32(smh);

    const int qt  = 15 - blockIdx.x;     // heavy tiles first
    const int nh  = blockIdx.y;
    const int b   = blockIdx.z;
    const int q0  = qt << 7;
    const int tid = threadIdx.x;
    const int lane = tid & 31;
    const int wid  = tid >> 5;
    const int g    = lane >> 2;
    const int t    = lane & 3;

    const size_t base_bh = ((size_t)b * S_LEN + (size_t)nh * HD) * QKV_N;
    const __half* vt_base = g_vt + (size_t)(b * NHEADS + nh) * HD * S_LEN;

    const int rowin = lane & 7;
    const int rsel  = (lane >> 3) & 1;
    const int csel  = (lane >> 4) & 1;
    const uint32_t q_lane_off =
        (uint32_t)(((wid * 16) + rsel * 8 + rowin) * AT_STR_H + csel * 8) * 2;
    const uint32_t k_lane_off =
        (uint32_t)((csel * 8 + rowin) * AT_STR_H + rsel * 8) * 2;
    const uint32_t v_lane_off =
        (uint32_t)((csel * 8 + rowin) * VT_STR_H + rsel * 8) * 2;

    auto fill_stage = [&](int kt, int s) {
        const int k0 = kt << 6;
        const uint32_t kb = smb + (uint32_t)(ATT_Q_H + s * ATT_STAGE_H) * 2;
        const uint32_t vb = kb + (uint32_t)ATT_K_H * 2;
#pragma unroll
        for (int i = 0; i < 4; i++) {
            const int slot = tid + (i << 8);
            const int r  = slot >> 4;
            const int ch = slot & 15;
            const int kg = k0 + r;
            cp16(kb + (uint32_t)(r * AT_STR_H + ch * 8) * 2,
                 g_qkv + base_bh + (size_t)(kg >> 4) * QKV_N + ((kg & 15) << 7) +
                 HDIM + ch * 8);
        }
#pragma unroll
        for (int i = 0; i < 4; i++) {
            const int slot = tid + (i << 8);
            const int d  = slot >> 3;
            const int ch = slot & 7;
            cp16(vb + (uint32_t)(d * VT_STR_H + ch * 8) * 2,
                 vt_base + (size_t)d * S_LEN + k0 + ch * 8);
        }
        CP_COMMIT();
    };

#pragma unroll
    for (int i = 0; i < 8; i++) {
        const int slot = tid + (i << 8);
        const int r  = slot >> 4;
        const int ch = slot & 15;
        const int qg = q0 + r;
        cp16(smb + (uint32_t)(r * AT_STR_H + ch * 8) * 2,
             g_qkv + base_bh + (size_t)(qg >> 4) * QKV_N + ((qg & 15) << 7) + ch * 8);
    }
    fill_stage(0, 0);
    CP_WAIT0();
    __syncthreads();

    float O[16][4];
#pragma unroll
    for (int nt = 0; nt < 16; nt++)
#pragma unroll
        for (int k = 0; k < 4; k++) O[nt][k] = 0.0f;

    float m_run[2] = {-1e30f, -1e30f};
    float l_run[2] = {0.0f, 0.0f};

    const int nkt = (q0 + 128) >> 6;

    for (int kt = 0; kt < nkt; kt++) {
        const int s  = kt & 1;
        const int k0 = kt << 6;
        const uint32_t Kcb = smb + (uint32_t)(ATT_Q_H + s * ATT_STAGE_H) * 2;
        const uint32_t Vcb = Kcb + (uint32_t)ATT_K_H * 2;
        const bool pre = (kt + 1) < nkt;

        if (pre) fill_stage(kt + 1, s ^ 1);

        // ---- S = Q K^T (16x64 per warp), 8 k16-steps ----
        float sacc[8][4];
#pragma unroll
        for (int nt = 0; nt < 8; nt++)
#pragma unroll
            for (int k = 0; k < 4; k++) sacc[nt][k] = 0.0f;

#pragma unroll
        for (int ks = 0; ks < 8; ks++) {
            const uint32_t kb = (uint32_t)ks * 32;
            uint32_t a[4];
            ldsm4(a, smb + q_lane_off + kb);
#pragma unroll
            for (int nt2 = 0; nt2 < 4; nt2++) {
                uint32_t rr[4];
                ldsm4(rr, Kcb + k_lane_off + kb + (uint32_t)(nt2 * 16 * AT_STR_H) * 2);
                uint32_t b0[2] = {rr[0], rr[1]};
                uint32_t b1[2] = {rr[2], rr[3]};
                mma_f16(sacc[2 * nt2],     a, b0);
                mma_f16(sacc[2 * nt2 + 1], a, b1);
            }
        }

        // ---- online softmax (base-2 domain; in-place exponentials) ----
        const bool crossing = (k0 + 63) > (q0 + (wid << 4));
        float corr[2];
#pragma unroll
        for (int r = 0; r < 2; r++) {
            const int qg = q0 + (wid << 4) + g + 8 * r;
            float rm = -1e30f;
#pragma unroll
            for (int nt = 0; nt < 8; nt++) {
#pragma unroll
                for (int j = 0; j < 2; j++) {
                    float v = sacc[nt][2 * r + j] * SCALE2;
                    if (crossing && (k0 + nt * 8 + 2 * t + j) > qg) v = -1.5e9f;
                    sacc[nt][2 * r + j] = v;
                    rm = fmaxf(rm, v);
                }
            }
            rm = fmaxf(rm, __shfl_xor_sync(0xffffffffu, rm, 1));
            rm = fmaxf(rm, __shfl_xor_sync(0xffffffffu, rm, 2));

            const float mn = fmaxf(m_run[r], rm);
            corr[r] = exp2f(m_run[r] - mn);
            m_run[r] = mn;

            float rs = 0.0f;
#pragma unroll
            for (int nt = 0; nt < 8; nt++) {
#pragma unroll
                for (int j = 0; j < 2; j++) {
                    const float p = exp2f(sacc[nt][2 * r + j] - mn);
                    sacc[nt][2 * r + j] = p;   // in place: P replaces scores
                    rs += p;
                }
            }
            rs += __shfl_xor_sync(0xffffffffu, rs, 1);
            rs += __shfl_xor_sync(0xffffffffu, rs, 2);
            l_run[r] = l_run[r] * corr[r] + rs;
        }
#pragma unroll
        for (int nt = 0; nt < 16; nt++) {
            O[nt][0] *= corr[0]; O[nt][1] *= corr[0];
            O[nt][2] *= corr[1]; O[nt][3] *= corr[1];
        }

        // ---- O += P V : P c-layout == fp16 A-layout (no shuffles) ----
#pragma unroll
        for (int ks = 0; ks < 4; ks++) {
            uint32_t a[4];
            a[0] = pack_h2(sacc[2 * ks][0],     sacc[2 * ks][1]);
            a[1] = pack_h2(sacc[2 * ks][2],     sacc[2 * ks][3]);
            a[2] = pack_h2(sacc[2 * ks + 1][0], sacc[2 * ks + 1][1]);
            a[3] = pack_h2(sacc[2 * ks + 1][2], sacc[2 * ks + 1][3]);
            const uint32_t kscol = (uint32_t)ks * 32;
#pragma unroll
            for (int nt2 = 0; nt2 < 8; nt2++) {
                uint32_t rr[4];
                ldsm4(rr, Vcb + v_lane_off + kscol +
                          (uint32_t)(nt2 * 16 * VT_STR_H) * 2);
                uint32_t b0[2] = {rr[0], rr[1]};
                uint32_t b1[2] = {rr[2], rr[3]};
                mma_f16(O[2 * nt2],     a, b0);
                mma_f16(O[2 * nt2 + 1], a, b1);
            }
        }

        CP_WAIT0();
        __syncthreads();
    }

#pragma unroll
    for (int r = 0; r < 2; r++) {
        const float inv = 1.0f / l_run[r];
        const int qg = q0 + (wid << 4) + g + 8 * r;
        __half* op = att_out + ((size_t)b * S_LEN + qg) * HDIM + nh * HD;
#pragma unroll
        for (int nt = 0; nt < 16; nt++) {
            __half2 h = __floats2half2_rn(O[nt][2 * r] * inv, O[nt][2 * r + 1] * inv);
            *(__half2*)(op + nt * 8 + 2 * t) = h;
        }
    }
}

// ---------------------------------------------------------------------------
// Launch
// ---------------------------------------------------------------------------
extern "C" void kernel_launch(void* const* d_in, const int* in_sizes, int n_in,
                              void* d_out, int out_size)
{
    const float* hidden = (const float*)d_in[0];
    const float* W_attn = (const float*)d_in[2];
    const float* b_attn = (const float*)d_in[3];
    const float* W_proj = (const float*)d_in[4];
    const float* b_proj = (const float*)d_in[5];
    float* out = (float*)d_out;

    __half *hid, *qkv, *att, *wta, *wtp;
    cudaGetSymbolAddress((void**)&hid, g_hid);
    cudaGetSymbolAddress((void**)&qkv, g_qkv);
    cudaGetSymbolAddress((void**)&att, g_att);
    cudaGetSymbolAddress((void**)&wta, g_wta);
    cudaGetSymbolAddress((void**)&wtp, g_wtp);

    const int M = BATCH * S_LEN;   // 4096

    // 0) Convert hidden to fp16; transpose+convert weights
    {
        const size_t n = (size_t)BATCH * S_LEN * HDIM;
        f2h_kernel<<<(int)(n / 8 / 256), 256>>>(hidden, hid);
        dim3 blk(32, 8);
        transpose_h_kernel<<<dim3(QKV_N / 32, HDIM / 32), blk>>>(W_attn, wta, HDIM, QKV_N);
        transpose_h_kernel<<<dim3(HDIM / 32, HDIM / 32), blk>>>(W_proj, wtp, HDIM, HDIM);
    }

    cudaFuncSetAttribute(gemm_f16_kernel,
                         cudaFuncAttributeMaxDynamicSharedMemorySize, GEMM_SMEM);

    // 1) QKV projection (fp16 out)
    gemm_f16_kernel<<<dim3(QKV_N / 128, M / 128), 256, GEMM_SMEM>>>(
        hid, wta, b_attn, qkv, M, QKV_N, HDIM, 1);

    // 1b) Per-head V transpose for PV ldmatrix path
    {
        dim3 blk(32, 8);
        vtranspose_kernel<<<dim3(S_LEN / 32, HD / 32, BATCH * NHEADS), blk>>>();
    }

    // 2) Attention (fp16 mma flash)
    {
        cudaFuncSetAttribute(attn_mma_kernel,
                             cudaFuncAttributeMaxDynamicSharedMemorySize, ATT_SMEM_B);
        dim3 grid(S_LEN / 128, NHEADS, BATCH);
        attn_mma_kernel<<<grid, 256, ATT_SMEM_B>>>(att);
    }

    // 3) Output projection (fp32 out)
    gemm_f16_kernel<<<dim3(HDIM / 128, M / 128), 256, GEMM_SMEM>>>(
        att, wtp, b_proj, out, M, HDIM, HDIM, 0);
}

// round 17
// speedup vs baseline: 1.0774x; 1.0222x over previous
#include <cuda_runtime.h>
#include <cuda_fp16.h>
#include <cstdint>
#include <cstddef>

// Problem constants
#define S_LEN   2048
#define HDIM    2048
#define NHEADS  16
#define HD      128
#define BATCH   2
#define QKV_N   6144
// SCALE * log2(e): softmax in base-2 domain; folded into Q at QKV epilogue.
#define SCALE2  0.12751649736230376f

// GEMM smem: 4 stages x (A 128x40h + B 128x40h)
#define GSTR_H      40
#define GSTAGE_H    (2 * 128 * GSTR_H)      // 10240 halves
#define GEMM_SMEM   (4 * GSTAGE_H * 2)      // 81920 B

// Attention smem: Q[128x136h] | stage{K[128x136h], Vt[128x136h]} x2
#define AT_STR_H    136
#define VT_STR_H    136
#define ATT_Q_H     (128 * AT_STR_H)        // 17408
#define ATT_K_H     (128 * AT_STR_H)        // 17408
#define ATT_VT_H    (128 * VT_STR_H)        // 17408
#define ATT_STAGE_H (ATT_K_H + ATT_VT_H)    // 34816
#define ATT_SMEM_B  ((ATT_Q_H + 2 * ATT_STAGE_H) * 2)  // 174080 B

// Scratch (device globals — allocation-free), all fp16
__device__ __half g_hid[(size_t)BATCH * S_LEN * HDIM];
__device__ __half g_qkv[(size_t)BATCH * S_LEN * QKV_N];
__device__ __half g_att[(size_t)BATCH * S_LEN * HDIM];
__device__ __half g_wta[(size_t)QKV_N * HDIM];
__device__ __half g_wtp[(size_t)HDIM * HDIM];
__device__ __half g_vt[(size_t)BATCH * NHEADS * HD * S_LEN];  // V^T per head [d][k]

__device__ __forceinline__ uint32_t smem_u32(const void* p) {
    uint32_t a;
    asm("{ .reg .u64 t; cvta.to.shared.u64 t, %1; cvt.u32.u64 %0, t; }" : "=r"(a) : "l"(p));
    return a;
}
__device__ __forceinline__ void cp16(uint32_t dst, const void* src) {
    asm volatile("cp.async.cg.shared.global [%0], [%1], 16;" :: "r"(dst), "l"(src));
}
#define CP_COMMIT() asm volatile("cp.async.commit_group;" ::: "memory")
#define CP_WAIT0()  asm volatile("cp.async.wait_group 0;" ::: "memory")

// m16n8k16 fp16 MMA, fp32 accumulate
__device__ __forceinline__ void mma_f16(float* c, const uint32_t* a, const uint32_t* b) {
    asm volatile(
        "mma.sync.aligned.m16n8k16.row.col.f32.f16.f16.f32 "
        "{%0,%1,%2,%3}, {%4,%5,%6,%7}, {%8,%9}, {%0,%1,%2,%3};"
        : "+f"(c[0]), "+f"(c[1]), "+f"(c[2]), "+f"(c[3])
        : "r"(a[0]), "r"(a[1]), "r"(a[2]), "r"(a[3]), "r"(b[0]), "r"(b[1]));
}
__device__ __forceinline__ void ldsm4(uint32_t* r, uint32_t addr) {
    asm volatile("ldmatrix.sync.aligned.m8n8.x4.shared.b16 {%0,%1,%2,%3}, [%4];"
                 : "=r"(r[0]), "=r"(r[1]), "=r"(r[2]), "=r"(r[3]) : "r"(addr));
}
__device__ __forceinline__ uint32_t pack_h2(float a, float b) {
    __half2 h = __floats2half2_rn(a, b);
    return *reinterpret_cast<uint32_t*>(&h);
}

// ---------------------------------------------------------------------------
// fp32 -> fp16 elementwise (8 per thread)
// ---------------------------------------------------------------------------
__global__ void f2h_kernel(const float* __restrict__ in, __half* __restrict__ out)
{
    const size_t i = ((size_t)blockIdx.x * blockDim.x + threadIdx.x) * 8;
    float4 v0 = *(const float4*)(in + i);
    float4 v1 = *(const float4*)(in + i + 4);
    __half2 h[4];
    h[0] = __floats2half2_rn(v0.x, v0.y);
    h[1] = __floats2half2_rn(v0.z, v0.w);
    h[2] = __floats2half2_rn(v1.x, v1.y);
    h[3] = __floats2half2_rn(v1.z, v1.w);
    *(uint4*)(out + i) = *(uint4*)h;
}

// ---------------------------------------------------------------------------
// Transpose fp32 -> fp16: out[C][R] = h(in[R][C])
// ---------------------------------------------------------------------------
__global__ void transpose_h_kernel(const float* __restrict__ in, __half* __restrict__ out,
                                   int R, int C)
{
    __shared__ float t[32][33];
    const int bx = blockIdx.x * 32;
    const int by = blockIdx.y * 32;
#pragma unroll
    for (int i = 0; i < 32; i += 8)
        t[threadIdx.y + i][threadIdx.x] =
            in[(size_t)(by + threadIdx.y + i) * C + bx + threadIdx.x];
    __syncthreads();
#pragma unroll
    for (int i = 0; i < 32; i += 8)
        out[(size_t)(bx + threadIdx.y + i) * R + by + threadIdx.x] =
            __float2half_rn(t[threadIdx.x][threadIdx.y + i]);
}

// ---------------------------------------------------------------------------
// V transpose (fp16): g_vt[(b*16+nh)*128 + d][k] = Vh[k][d]
// ---------------------------------------------------------------------------
__global__ void vtranspose_kernel(void)
{
    __shared__ __half t[32][34];
    const int tk = blockIdx.x * 32;
    const int td = blockIdx.y * 32;
    const int h  = blockIdx.z;
    const int b  = h >> 4;
    const int nh = h & 15;

    const size_t base_bh = ((size_t)b * S_LEN + (size_t)nh * HD) * QKV_N + 2 * HDIM;
#pragma unroll
    for (int i = 0; i < 32; i += 8) {
        const int k = tk + threadIdx.y + i;
        t[threadIdx.y + i][threadIdx.x] =
            g_qkv[base_bh + (size_t)(k >> 4) * QKV_N + ((k & 15) << 7) + td + threadIdx.x];
    }
    __syncthreads();
#pragma unroll
    for (int i = 0; i < 32; i += 8)
        g_vt[((size_t)h * HD + td + threadIdx.y + i) * S_LEN + tk + threadIdx.x] =
            t[threadIdx.x][threadIdx.y + i];
}

// ---------------------------------------------------------------------------
// fp16 mma.sync GEMM (locked config): 256 threads, warp 64x32, cp.async
// 4-stage, pair-chunk barriers, LDSM fragments. C = A @ Bt^T + bias.
// out_half==1 additionally prescales Q columns (col < HDIM) by SCALE2.
// ---------------------------------------------------------------------------
__global__ __launch_bounds__(256, 2)
void gemm_f16_kernel(const __half* __restrict__ A, const __half* __restrict__ Bt,
                     const float* __restrict__ bias, void* Cv,
                     int M, int N, int K, int out_half)
{
    extern __shared__ __half smh[];
    const uint32_t smb = smem_u32(smh);
    const int tid    = threadIdx.x;
    const int lane   = tid & 31;
    const int wid    = tid >> 5;
    const int g      = lane >> 2;
    const int t      = lane & 3;
    const int warp_m = wid & 1;
    const int warp_n = wid >> 1;
    const int m0     = blockIdx.y << 7;
    const int n0     = blockIdx.x << 7;

    const __half* Ap = A  + (size_t)m0 * K;
    const __half* Bp = Bt + (size_t)n0 * K;

    const int nchunks = K >> 5;       // 32 halves per chunk
    const int npairs  = nchunks >> 1;
    const int fr  = tid >> 2;         // fill row 0..63 (x2)
    const int fc  = tid & 3;          // 16B chunk within 64B row

    const int rowin = lane & 7;
    const int rsel  = (lane >> 3) & 1;
    const int csel  = (lane >> 4) & 1;

    const uint32_t a_lane_off =
        (uint32_t)(((warp_m * 64) + rsel * 8 + rowin) * GSTR_H + csel * 8) * 2;
    const uint32_t b_lane_off =
        (uint32_t)(((warp_n * 32) + csel * 8 + rowin) * GSTR_H + rsel * 8) * 2;

    auto fill = [&](int c, int s) {
        if (c < nchunks) {
            const int kc = c << 5;
            const uint32_t sa = smb + (uint32_t)s * GSTAGE_H * 2;
#pragma unroll
            for (int i = 0; i < 2; i++) {
                const int r = fr + (i << 6);
                cp16(sa + (uint32_t)(r * GSTR_H + fc * 8) * 2,
                     Ap + (size_t)r * K + kc + fc * 8);
                cp16(sa + (uint32_t)(128 * GSTR_H + r * GSTR_H + fc * 8) * 2,
                     Bp + (size_t)r * K + kc + fc * 8);
            }
        }
        CP_COMMIT();
    };

    float acc[4][4][4];
#pragma unroll
    for (int mt = 0; mt < 4; mt++)
#pragma unroll
        for (int nt = 0; nt < 4; nt++)
#pragma unroll
            for (int k = 0; k < 4; k++) acc[mt][nt][k] = 0.0f;

    float2 bv[4];
#pragma unroll
    for (int nt = 0; nt < 4; nt++)
        bv[nt] = *(const float2*)(bias + n0 + warp_n * 32 + nt * 8 + 2 * t);

    fill(0, 0); fill(1, 1);

    for (int p = 0; p < npairs; ++p) {
        const int c0 = p << 1;
        CP_WAIT0();
        __syncthreads();
        fill(c0 + 2, (c0 + 2) & 3);
        fill(c0 + 3, (c0 + 3) & 3);

#pragma unroll
        for (int half = 0; half < 2; ++half) {
            const int s = (c0 + half) & 3;
            const uint32_t sAb = smb + (uint32_t)s * GSTAGE_H * 2;
            const uint32_t sBb = sAb + 128 * GSTR_H * 2;
#pragma unroll
            for (int ks = 0; ks < 2; ks++) {          // k16 steps
                const uint32_t kb = (uint32_t)ks * 32;  // 16 halves
                uint32_t afr[4][4], bfr[4][2];
#pragma unroll
                for (int mt = 0; mt < 4; mt++)
                    ldsm4(afr[mt], sAb + a_lane_off + kb +
                                   (uint32_t)(mt * 16 * GSTR_H) * 2);
#pragma unroll
                for (int nt2 = 0; nt2 < 2; nt2++) {
                    uint32_t rr[4];
                    ldsm4(rr, sBb + b_lane_off + kb +
                              (uint32_t)(nt2 * 16 * GSTR_H) * 2);
                    bfr[2 * nt2][0]     = rr[0];
                    bfr[2 * nt2][1]     = rr[1];
                    bfr[2 * nt2 + 1][0] = rr[2];
                    bfr[2 * nt2 + 1][1] = rr[3];
                }
#pragma unroll
                for (int mt = 0; mt < 4; mt++)
#pragma unroll
                    for (int nt = 0; nt < 4; nt++)
                        mma_f16(acc[mt][nt], afr[mt], bfr[nt]);
            }
        }
    }

    // Prescale Q columns (uniform per CTA: 2048 is a 128-tile boundary)
    const float oscale = (out_half && n0 < HDIM) ? SCALE2 : 1.0f;

#pragma unroll
    for (int mt = 0; mt < 4; mt++) {
        const int row0 = m0 + warp_m * 64 + mt * 16 + g;
#pragma unroll
        for (int nt = 0; nt < 4; nt++) {
            const int col = n0 + warp_n * 32 + nt * 8 + 2 * t;
            const float x0 = (acc[mt][nt][0] + bv[nt].x) * oscale;
            const float y0 = (acc[mt][nt][1] + bv[nt].y) * oscale;
            const float x1 = (acc[mt][nt][2] + bv[nt].x) * oscale;
            const float y1 = (acc[mt][nt][3] + bv[nt].y) * oscale;
            if (out_half) {
                __half* C = (__half*)Cv;
                *(__half2*)(C + (size_t)row0 * N + col)       = __floats2half2_rn(x0, y0);
                *(__half2*)(C + (size_t)(row0 + 8) * N + col) = __floats2half2_rn(x1, y1);
            } else {
                float* C = (float*)Cv;
                *(float2*)(C + (size_t)row0 * N + col)       = make_float2(x0, y0);
                *(float2*)(C + (size_t)(row0 + 8) * N + col) = make_float2(x1, y1);
            }
        }
    }
}

// ---------------------------------------------------------------------------
// Flash attention, fp16 mma.sync m16n8k16, kv-tile 128 (softmax overhead paid
// once per 128 keys). Q prescaled by SCALE2 at the QKV epilogue.
// Smem: Q[128x136] | stage{K[128x136], Vt[128x136]} x2 = 174080 B, 1 CTA/SM.
// ---------------------------------------------------------------------------
__global__ __launch_bounds__(256, 1)
void attn_mma_kernel(__half* __restrict__ att_out)
{
    extern __shared__ __half smh[];
    const uint32_t smb = smem_u32(smh);

    const int qt  = 15 - blockIdx.x;     // heavy tiles first
    const int nh  = blockIdx.y;
    const int b   = blockIdx.z;
    const int q0  = qt << 7;
    const int tid = threadIdx.x;
    const int lane = tid & 31;
    const int wid  = tid >> 5;
    const int g    = lane >> 2;
    const int t    = lane & 3;

    const size_t base_bh = ((size_t)b * S_LEN + (size_t)nh * HD) * QKV_N;
    const __half* vt_base = g_vt + (size_t)(b * NHEADS + nh) * HD * S_LEN;

    const int rowin = lane & 7;
    const int rsel  = (lane >> 3) & 1;
    const int csel  = (lane >> 4) & 1;
    const uint32_t q_lane_off =
        (uint32_t)(((wid * 16) + rsel * 8 + rowin) * AT_STR_H + csel * 8) * 2;
    const uint32_t k_lane_off =
        (uint32_t)((csel * 8 + rowin) * AT_STR_H + rsel * 8) * 2;
    const uint32_t v_lane_off =
        (uint32_t)((csel * 8 + rowin) * VT_STR_H + rsel * 8) * 2;

    // stage fill: K tile (128x128h) + Vt tile (128x128h)
    auto fill_stage = [&](int kt, int s) {
        const int k0 = kt << 7;
        const uint32_t kb = smb + (uint32_t)(ATT_Q_H + s * ATT_STAGE_H) * 2;
        const uint32_t vb = kb + (uint32_t)ATT_K_H * 2;
#pragma unroll
        for (int i = 0; i < 8; i++) {            // K: 2048 16B-chunks
            const int slot = tid + (i << 8);
            const int r  = slot >> 4;
            const int ch = slot & 15;
            const int kg = k0 + r;
            cp16(kb + (uint32_t)(r * AT_STR_H + ch * 8) * 2,
                 g_qkv + base_bh + (size_t)(kg >> 4) * QKV_N + ((kg & 15) << 7) +
                 HDIM + ch * 8);
        }
#pragma unroll
        for (int i = 0; i < 8; i++) {            // Vt: 2048 16B-chunks
            const int slot = tid + (i << 8);
            const int d  = slot >> 4;
            const int ch = slot & 15;
            cp16(vb + (uint32_t)(d * VT_STR_H + ch * 8) * 2,
                 vt_base + (size_t)d * S_LEN + k0 + ch * 8);
        }
        CP_COMMIT();
    };

    // ---- Q fill (prescaled by SCALE2 already) ----
#pragma unroll
    for (int i = 0; i < 8; i++) {
        const int slot = tid + (i << 8);
        const int r  = slot >> 4;
        const int ch = slot & 15;
        const int qg = q0 + r;
        cp16(smb + (uint32_t)(r * AT_STR_H + ch * 8) * 2,
             g_qkv + base_bh + (size_t)(qg >> 4) * QKV_N + ((qg & 15) << 7) + ch * 8);
    }
    fill_stage(0, 0);
    CP_WAIT0();
    __syncthreads();

    float O[16][4];
#pragma unroll
    for (int nt = 0; nt < 16; nt++)
#pragma unroll
        for (int k = 0; k < 4; k++) O[nt][k] = 0.0f;

    float m_run[2] = {-1e30f, -1e30f};
    float l_run[2] = {0.0f, 0.0f};

    const int nkt = qt + 1;

    for (int kt = 0; kt < nkt; kt++) {
        const int s  = kt & 1;
        const int k0 = kt << 7;
        const uint32_t Kcb = smb + (uint32_t)(ATT_Q_H + s * ATT_STAGE_H) * 2;
        const uint32_t Vcb = Kcb + (uint32_t)ATT_K_H * 2;
        const bool pre = (kt + 1) < nkt;

        if (pre) fill_stage(kt + 1, s ^ 1);

        // ---- S = Q K^T (16x128 per warp), 8 k16-steps ----
        float sacc[16][4];
#pragma unroll
        for (int nt = 0; nt < 16; nt++)
#pragma unroll
            for (int k = 0; k < 4; k++) sacc[nt][k] = 0.0f;

#pragma unroll
        for (int ks = 0; ks < 8; ks++) {
            const uint32_t kb = (uint32_t)ks * 32;   // 16 halves
            uint32_t a[4];
            ldsm4(a, smb + q_lane_off + kb);
#pragma unroll
            for (int nt2 = 0; nt2 < 8; nt2++) {
                uint32_t rr[4];
                ldsm4(rr, Kcb + k_lane_off + kb + (uint32_t)(nt2 * 16 * AT_STR_H) * 2);
                uint32_t b0[2] = {rr[0], rr[1]};
                uint32_t b1[2] = {rr[2], rr[3]};
                mma_f16(sacc[2 * nt2],     a, b0);
                mma_f16(sacc[2 * nt2 + 1], a, b1);
            }
        }

        // ---- online softmax (base-2; scores pre-scaled; in-place P) ----
        const bool diag = (kt == qt);
        float corr[2];
#pragma unroll
        for (int r = 0; r < 2; r++) {
            const int qg = q0 + (wid << 4) + g + 8 * r;
            float rm = -1e30f;
#pragma unroll
            for (int nt = 0; nt < 16; nt++) {
#pragma unroll
                for (int j = 0; j < 2; j++) {
                    float v = sacc[nt][2 * r + j];
                    if (diag && (k0 + nt * 8 + 2 * t + j) > qg) v = -1.5e9f;
                    sacc[nt][2 * r + j] = v;
                    rm = fmaxf(rm, v);
                }
            }
            rm = fmaxf(rm, __shfl_xor_sync(0xffffffffu, rm, 1));
            rm = fmaxf(rm, __shfl_xor_sync(0xffffffffu, rm, 2));

            const float mn = fmaxf(m_run[r], rm);
            corr[r] = exp2f(m_run[r] - mn);
            m_run[r] = mn;

            float rs = 0.0f;
#pragma unroll
            for (int nt = 0; nt < 16; nt++) {
#pragma unroll
                for (int j = 0; j < 2; j++) {
                    const float p = exp2f(sacc[nt][2 * r + j] - mn);
                    sacc[nt][2 * r + j] = p;   // in place: P replaces scores
                    rs += p;
                }
            }
            rs += __shfl_xor_sync(0xffffffffu, rs, 1);
            rs += __shfl_xor_sync(0xffffffffu, rs, 2);
            l_run[r] = l_run[r] * corr[r] + rs;
        }
#pragma unroll
        for (int nt = 0; nt < 16; nt++) {
            O[nt][0] *= corr[0]; O[nt][1] *= corr[0];
            O[nt][2] *= corr[1]; O[nt][3] *= corr[1];
        }

        // ---- O += P V : P c-layout == fp16 A-layout (no shuffles) ----
#pragma unroll
        for (int ks = 0; ks < 8; ks++) {          // 8 k16-steps over 128 keys
            uint32_t a[4];
            a[0] = pack_h2(sacc[2 * ks][0],     sacc[2 * ks][1]);
            a[1] = pack_h2(sacc[2 * ks][2],     sacc[2 * ks][3]);
            a[2] = pack_h2(sacc[2 * ks + 1][0], sacc[2 * ks + 1][1]);
            a[3] = pack_h2(sacc[2 * ks + 1][2], sacc[2 * ks + 1][3]);
            const uint32_t kscol = (uint32_t)ks * 32;
#pragma unroll
            for (int nt2 = 0; nt2 < 8; nt2++) {
                uint32_t rr[4];
                ldsm4(rr, Vcb + v_lane_off + kscol +
                          (uint32_t)(nt2 * 16 * VT_STR_H) * 2);
                uint32_t b0[2] = {rr[0], rr[1]};
                uint32_t b1[2] = {rr[2], rr[3]};
                mma_f16(O[2 * nt2],     a, b0);
                mma_f16(O[2 * nt2 + 1], a, b1);
            }
        }

        CP_WAIT0();
        __syncthreads();
    }

    // ---- epilogue: normalize, write fp16 [b][q][nh*128 + d] ----
#pragma unroll
    for (int r = 0; r < 2; r++) {
        const float inv = 1.0f / l_run[r];
        const int qg = q0 + (wid << 4) + g + 8 * r;
        __half* op = att_out + ((size_t)b * S_LEN + qg) * HDIM + nh * HD;
#pragma unroll
        for (int nt = 0; nt < 16; nt++) {
            __half2 h = __floats2half2_rn(O[nt][2 * r] * inv, O[nt][2 * r + 1] * inv);
            *(__half2*)(op + nt * 8 + 2 * t) = h;
        }
    }
}

// ---------------------------------------------------------------------------
// Launch
// ---------------------------------------------------------------------------
extern "C" void kernel_launch(void* const* d_in, const int* in_sizes, int n_in,
                              void* d_out, int out_size)
{
    const float* hidden = (const float*)d_in[0];
    const float* W_attn = (const float*)d_in[2];
    const float* b_attn = (const float*)d_in[3];
    const float* W_proj = (const float*)d_in[4];
    const float* b_proj = (const float*)d_in[5];
    float* out = (float*)d_out;

    __half *hid, *qkv, *att, *wta, *wtp;
    cudaGetSymbolAddress((void**)&hid, g_hid);
    cudaGetSymbolAddress((void**)&qkv, g_qkv);
    cudaGetSymbolAddress((void**)&att, g_att);
    cudaGetSymbolAddress((void**)&wta, g_wta);
    cudaGetSymbolAddress((void**)&wtp, g_wtp);

    const int M = BATCH * S_LEN;   // 4096

    // 0) Convert hidden to fp16; transpose+convert weights
    {
        const size_t n = (size_t)BATCH * S_LEN * HDIM;
        f2h_kernel<<<(int)(n / 8 / 256), 256>>>(hidden, hid);
        dim3 blk(32, 8);
        transpose_h_kernel<<<dim3(QKV_N / 32, HDIM / 32), blk>>>(W_attn, wta, HDIM, QKV_N);
        transpose_h_kernel<<<dim3(HDIM / 32, HDIM / 32), blk>>>(W_proj, wtp, HDIM, HDIM);
    }

    cudaFuncSetAttribute(gemm_f16_kernel,
                         cudaFuncAttributeMaxDynamicSharedMemorySize, GEMM_SMEM);

    // 1) QKV projection (fp16 out; Q columns prescaled by SCALE2)
    gemm_f16_kernel<<<dim3(QKV_N / 128, M / 128), 256, GEMM_SMEM>>>(
        hid, wta, b_attn, qkv, M, QKV_N, HDIM, 1);

    // 1b) Per-head V transpose for PV ldmatrix path
    {
        dim3 blk(32, 8);
        vtranspose_kernel<<<dim3(S_LEN / 32, HD / 32, BATCH * NHEADS), blk>>>();
    }

    // 2) Attention (fp16 mma flash, kv-tile 128)
    {
        cudaFuncSetAttribute(attn_mma_kernel,
                             cudaFuncAttributeMaxDynamicSharedMemorySize, ATT_SMEM_B);
        dim3 grid(S_LEN / 128, NHEADS, BATCH);
        attn_mma_kernel<<<grid, 256, ATT_SMEM_B>>>(att);
    }

    // 3) Output projection (fp32 out)
    gemm_f16_kernel<<<dim3(HDIM / 128, M / 128), 256, GEMM_SMEM>>>(
        att, wtp, b_proj, out, M, HDIM, HDIM, 0);
}